// round 14
// baseline (speedup 1.0000x reference)
#include <cuda_runtime.h>
#include <cuda_bf16.h>
#include <math.h>

#define NB 64
#define NN 512
#define GRID 296
#define NWARP (GRID * 8)            // 2368
#define NGRP 37                     // 296 / 8
#define LN2 0.6931471805599453

// Scratch (__device__ globals; zeroed at load; re-zeroed by the last block)
__device__ double g_pair[NB][8];    // [2]=dot [3]=na2 [4]=aSum [5]=ent(log2) [6]=con
__device__ double g_part[GRID][4];  // per-block partials: edge, sim, mse, smooth
__device__ int    g_done1[NGRP];
__device__ int    g_done2;

// ---------------------------------------------------------------------------
// masked element op (last strip only): identity when !vb
__device__ __forceinline__ void lean_m(float p, float a, float s, bool vb,
                                       float& Px, float& Py, float& sim) {
    float w  = fmaf(-2.0f, p, 1.0f);
    float x0 = fmaf(a, w, p);
    float x  = vb ? x0 : 1.0f;
    float y  = vb ? 1.0f - x0 : 1.0f;
    float d  = vb ? s - a : 0.0f;
    Px *= x;
    Py *= y;
    sim = fmaf(d, d, sim);
}
// unmasked element op (strips known fully valid)
__device__ __forceinline__ void lean_u(float p, float a, float s,
                                       float& Px, float& Py, float& sim) {
    float x = fmaf(a, fmaf(-2.0f, p, 1.0f), p);
    Px *= x;
    Py *= 1.0f - x;
    float d = s - a;
    sim = fmaf(d, d, sim);
}

// ---------------------------------------------------------------------------
// One lean row with NS strips (NS = ceil(cnt4/32), 1..4).
template<int NS>
__device__ __forceinline__ void lean_row(
        const float4* __restrict__ pr, const float4* __restrict__ ar,
        const float4* __restrict__ sr, int lane, int cnt, int cnt4,
        double& accE, double& accS) {
    float Px = 1.f, Py = 1.f, sim = 0.f;
    const int cl = lane + 32 * (NS - 1);
    const int kl = min(cl, cnt4 - 1);
    float4 P[NS], A[NS], S[NS];
    #pragma unroll
    for (int k = 0; k < NS - 1; ++k) P[k] = __ldg(pr + lane + 32 * k);
    P[NS - 1] = __ldg(pr + kl);
    #pragma unroll
    for (int k = 0; k < NS - 1; ++k) A[k] = __ldg(ar + lane + 32 * k);
    A[NS - 1] = __ldg(ar + kl);
    #pragma unroll
    for (int k = 0; k < NS - 1; ++k) S[k] = __ldg(sr + lane + 32 * k);
    S[NS - 1] = __ldg(sr + kl);
    #pragma unroll
    for (int k = 0; k < NS - 1; ++k) {
        lean_u(P[k].x, A[k].x, S[k].x, Px, Py, sim);
        lean_u(P[k].y, A[k].y, S[k].y, Px, Py, sim);
        lean_u(P[k].z, A[k].z, S[k].z, Px, Py, sim);
        lean_u(P[k].w, A[k].w, S[k].w, Px, Py, sim);
    }
    lean_m(P[NS-1].x, A[NS-1].x, S[NS-1].x, 4 * cl + 0 < cnt, Px, Py, sim);
    lean_m(P[NS-1].y, A[NS-1].y, S[NS-1].y, 4 * cl + 1 < cnt, Px, Py, sim);
    lean_m(P[NS-1].z, A[NS-1].z, S[NS-1].z, 4 * cl + 2 < cnt, Px, Py, sim);
    lean_m(P[NS-1].w, A[NS-1].w, S[NS-1].w, 4 * cl + 3 < cnt, Px, Py, sim);
    accE += (double)fmaf(0.05f, __log2f(Px), 0.95f * __log2f(Py));
    accS += (double)sim;
}

// ---------------------------------------------------------------------------
__global__ __launch_bounds__(256, 2) void fused_kernel(
        const float* __restrict__ pc,      const float* __restrict__ adjm,
        const float* __restrict__ ncounts, const float* __restrict__ rsim,
        const float* __restrict__ temp,    const float* __restrict__ resw,
        const float* __restrict__ pts,     const float* __restrict__ adj,
        const void*  mask_raw,             float* __restrict__ out) {
    const int tid  = threadIdx.x;
    const int lane = tid & 31;
    const int w    = tid >> 5;
    const unsigned full = 0xffffffffu;

    __shared__ int s_cnt[NB];
    __shared__ int s_pref[NB + 1];

    // ---- all 64 mask counts. Fast path (uint8 mask): ONE independent load
    // round (8 x uint4 per lane-warp) + REDUX. Fallback: 2 ballot rounds. ----
    {
        const unsigned char* mb = (const unsigned char*)mask_raw;
        // speculative batched loads (addresses independent of mode)
        const uint4* m16 = (const uint4*)mask_raw;
        uint4 v[8];
        #pragma unroll
        for (int q = 0; q < 8; ++q)
            v[q] = __ldg(m16 + (w * 8 + q) * 32 + lane);
        unsigned char c0 = mb[0], c1 = mb[1];   // elem (0,0) is always true
        int mode = (c1 != 0) ? 0 : ((c0 != 0) ? 1 : 2);
        if (mode == 0) {
            #pragma unroll
            for (int q = 0; q < 8; ++q) {
                int c = (__popc(__vcmpne4(v[q].x, 0u)) + __popc(__vcmpne4(v[q].y, 0u))
                       + __popc(__vcmpne4(v[q].z, 0u)) + __popc(__vcmpne4(v[q].w, 0u))) >> 3;
                c = __reduce_add_sync(full, c);
                if (lane == 0) s_cnt[w * 8 + q] = c;
            }
        } else {
            auto rd = [&](int idx) -> bool {
                if (mode == 1) return ((const int*)mask_raw)[idx] != 0;
                else           return ((const float*)mask_raw)[idx] != 0.0f;
            };
            #pragma unroll
            for (int q = 0; q < 8; ++q) {
                bool on1 = rd((w * 8 + q) * NN + lane * 16 + 15);
                int k = __popc(__ballot_sync(full, on1));
                bool on2 = (k < 32 && lane < 16)
                         ? rd((w * 8 + q) * NN + 16 * k + lane) : false;
                unsigned bal = __ballot_sync(full, on2);
                int c = (k == 32) ? NN : 16 * k + __popc(bal & 0xFFFFu);
                if (lane == 0) s_cnt[w * 8 + q] = c;
            }
        }
    }
    __syncthreads();

    // ---- prefix sum over the 64 counts (warp 0) ----
    if (w == 0) {
        int v0 = s_cnt[lane], v1 = s_cnt[lane + 32];
        int a0 = v0;
        #pragma unroll
        for (int o = 1; o < 32; o <<= 1) {
            int t = __shfl_up_sync(full, a0, o);
            if (lane >= o) a0 += t;
        }
        int tot0 = __shfl_sync(full, a0, 31);
        int a1 = v1;
        #pragma unroll
        for (int o = 1; o < 32; o <<= 1) {
            int t = __shfl_up_sync(full, a1, o);
            if (lane >= o) a1 += t;
        }
        a1 += tot0;
        s_pref[lane + 1]  = a0;
        s_pref[lane + 33] = a1;
        if (lane == 0) s_pref[0] = 0;
    }
    __syncthreads();
    const int R = s_pref[NB];

    double accE = 0.0, accS = 0.0, accM = 0.0, accSm = 0.0;
    const int gw = blockIdx.x * 8 + w;

    for (int u = gw; u < R + NB; u += NWARP) {
        if (u < R) {
            int lo = 0, hi = NB;
            #pragma unroll
            for (int it = 0; it < 6; ++it) {
                int mid = (lo + hi) >> 1;
                if (s_pref[mid] <= u) lo = mid; else hi = mid;
            }
            const int b   = lo;
            const int i   = u - s_pref[lo];
            const int cnt = s_cnt[b];
            const size_t rb = ((size_t)b * NN + i) * NN;

            if (cnt > 50) {
                const float4* pr = (const float4*)(adjm + rb);
                const float4* ar = (const float4*)(adj  + rb);
                const float4* sr = (const float4*)(rsim + rb);
                const int cnt4 = (cnt + 3) >> 2;
                const int ns = (cnt4 + 31) >> 5;
                switch (ns) {
                    case 1: lean_row<1>(pr, ar, sr, lane, cnt, cnt4, accE, accS); break;
                    case 2: lean_row<2>(pr, ar, sr, lane, cnt, cnt4, accE, accS); break;
                    case 3: lean_row<3>(pr, ar, sr, lane, cnt, cnt4, accE, accS); break;
                    default: lean_row<4>(pr, ar, sr, lane, cnt, cnt4, accE, accS); break;
                }
            } else {
                const int j0 = lane, j1 = lane + 32;
                const int mm = cnt - 1;
                const int k0 = min(j0, mm), k1 = min(j1, mm);
                float p0 = __ldg(adjm + rb + k0);
                float p1 = __ldg(adjm + rb + k1);
                float a0 = __ldg(adj  + rb + k0);
                float a1 = __ldg(adj  + rb + k1);
                float s0 = __ldg(rsim + rb + k0);
                float s1 = __ldg(rsim + rb + k1);
                const bool i0 = j0 >= cnt, i1 = j1 >= cnt;
                p0 = i0 ? 0.5f : p0;  a0 = i0 ? 0.f : a0;  s0 = i0 ? 0.f : s0;
                p1 = i1 ? 0.5f : p1;  a1 = i1 ? 0.f : a1;  s1 = i1 ? 0.f : s1;
                float sL=0,sM=0,sAt=0,sSim=0,sDot=0,sP2=0,sA=0,sPt=0,sCon=0;
                #pragma unroll
                for (int e = 0; e < 2; ++e) {
                    float p = e ? p1 : p0, a = e ? a1 : a0, s = e ? s1 : s0;
                    float L = __log2f(p), M = __log2f(1.0f - p);
                    float t = L - M;
                    sL += L; sM += M;
                    sAt = fmaf(a, t, sAt);
                    float ds = s - a;
                    sSim = fmaf(ds, ds, sSim);
                    sDot = fmaf(p, a, sDot);
                    sP2  = fmaf(p, p, sP2);
                    sA  += a;
                    sPt  = fmaf(p, t, sPt);
                    sCon += fabsf(p - 0.5f);
                }
                float inv = (i0 ? 1.f : 0.f) + (i1 ? 1.f : 0.f);
                sL += inv; sM += inv; sP2 -= 0.25f * inv;
                accE += (double)fmaf(0.05f, sL, fmaf(0.95f, sM, 0.9f * sAt));
                accS += (double)sSim;
                float v5[5] = {sDot, sP2, sA, sM + sPt, sCon};
                #pragma unroll
                for (int k = 0; k < 5; ++k)
                    #pragma unroll
                    for (int o = 16; o; o >>= 1)
                        v5[k] += __shfl_down_sync(full, v5[k], o);
                if (lane == 0) {
                    atomicAdd(&g_pair[b][2], (double)v5[0]);
                    atomicAdd(&g_pair[b][3], (double)v5[1]);
                    atomicAdd(&g_pair[b][4], (double)v5[2]);
                    atomicAdd(&g_pair[b][5], (double)v5[3]);
                    atomicAdd(&g_pair[b][6], (double)v5[4]);
                }
            }
        } else {
            const int b   = u - R;
            const int cnt = s_cnt[b];
            const float2* pc2  = (const float2*)pc + (size_t)b * NN;
            const float2* pts2 = (const float2*)pts + (size_t)b * NN;
            const int mm = cnt - 1;
            float mse = 0.f, smo = 0.f;
            for (int n0 = lane; n0 < cnt; n0 += 128) {
                const int n1 = n0 + 32, n2 = n0 + 64, n3 = n0 + 96;
                const int q1 = min(n1, mm);
                const int q2 = min(n2, mm), q3 = min(n3, mm);
                float2 u0 = __ldg(pc2 + n0);
                float2 u1 = __ldg(pc2 + q1);
                float2 u2 = __ldg(pc2 + q2);
                float2 u3 = __ldg(pc2 + q3);
                float2 v0 = __ldg(pts2 + n0);
                float2 v1 = __ldg(pts2 + q1);
                float2 v2 = __ldg(pts2 + q2);
                float2 v3 = __ldg(pts2 + q3);
                #define COORD1(UU,VV,NI) do {                                 \
                    bool vz = (NI) < cnt;                                     \
                    float dx = vz ? (UU.x - VV.x) : 0.f;                      \
                    float dy = vz ? (UU.y - VV.y) : 0.f;                      \
                    mse += dx * dx + dy * dy;                                 \
                    float ax = fabsf(dx), ay = fabsf(dy);                     \
                    smo += (ax < 1.0f ? 0.5f * dx * dx : ax - 0.5f)           \
                         + (ay < 1.0f ? 0.5f * dy * dy : ay - 0.5f); } while(0)
                COORD1(u0, v0, n0);
                COORD1(u1, v1, n1);
                COORD1(u2, v2, n2);
                COORD1(u3, v3, n3);
                #undef COORD1
            }
            accM  += (double)mse;
            accSm += (double)smo;
        }
    }

    // ---- block-reduce of the 4 accumulators -> contention-free STG ----
    {
        __shared__ double sh[8][4];
        double v[4] = {accE, accS, accM, accSm};
        #pragma unroll
        for (int k = 0; k < 4; ++k) {
            #pragma unroll
            for (int o = 16; o; o >>= 1) v[k] += __shfl_down_sync(full, v[k], o);
            if (lane == 0) sh[w][k] = v[k];
        }
        __syncthreads();
        if (w == 0 && lane < 4) {
            double xx = 0.0;
            #pragma unroll
            for (int ww = 0; ww < 8; ++ww) xx += sh[ww][lane];
            g_part[blockIdx.x][lane] = xx;        // plain STG, no contention
            __threadfence();                       // writer-side release
        }
    }

    // ---- hierarchical completion counter: 8-deep + 37-deep chains ----
    __shared__ int s_last;
    __threadfence();              // order g_pair atomics (any thread) too
    __syncthreads();
    if (tid == 0) {
        s_last = 0;
        const int g = blockIdx.x >> 3;            // 37 groups of 8
        int o1 = atomicAdd(&g_done1[g], 1);
        if (o1 == 7) {
            int o2 = atomicAdd(&g_done2, 1);
            if (o2 == NGRP - 1) s_last = 1;
        }
    }
    __syncthreads();
    if (!s_last) return;
    __threadfence();

    // ---- finalize (last block only) ----
    // sum contention-free partials: 296 blocks x 4 doubles
    double pe = 0.0, ps = 0.0, pm = 0.0, psm = 0.0;
    for (int blk = tid; blk < GRID; blk += 256) {
        pe  += g_part[blk][0];
        ps  += g_part[blk][1];
        pm  += g_part[blk][2];
        psm += g_part[blk][3];
    }
    // per-batch quantities (thread t < NB handles batch t)
    double c2 = 0.0, cntd = 0.0, cl = 0.0, ac = 0.0;
    if (tid < NB) {
        int ci = s_cnt[tid];
        cntd   = (double)ci;
        c2     = cntd * cntd;
        double dc  = (double)__ldg(ncounts + tid) - cntd;
        double adc = fabs(dc);
        cl = (adc <= 1.0) ? 0.5 * dc * dc : adc - 0.5;
        if (ci > 5 && ci <= 50) {
            double dot  = g_pair[tid][2];
            double na2  = g_pair[tid][3];
            double nt2  = g_pair[tid][4];
            double entn = g_pair[tid][5] * LN2;
            double con  = g_pair[tid][6];
            double na   = sqrt(na2), nt = sqrt(nt2);
            double cosv = dot / (fmax(na, 1e-8) * fmax(nt, 1e-8));
            double n2   = fmax(c2, 1.0);
            ac = (-cosv - 0.2 * (con / n2)) + 0.1 * (-entn / n2);
        }
    }
    {
        __shared__ double sh2[8][8];
        double v[8] = {c2, cntd, cl, ac, pe, ps, pm, psm};
        #pragma unroll
        for (int k = 0; k < 8; ++k) {
            #pragma unroll
            for (int o = 16; o; o >>= 1) v[k] += __shfl_down_sync(full, v[k], o);
            if (lane == 0) sh2[w][k] = v[k];
        }
        __syncthreads();
        if (tid == 0) {
            double t8[8];
            #pragma unroll
            for (int k = 0; k < 8; ++k) {
                double xx = 0.0;
                #pragma unroll
                for (int ww = 0; ww < 8; ++ww) xx += sh2[ww][k];
                t8[k] = xx;
            }
            double cnt2       = fmax(t8[0], 1.0);
            double cnt_coord  = fmax(t8[1] * 2.0, 1.0);
            double edge_loss  = -(t8[4] * LN2) / cnt2;
            double sim_loss   = t8[5] / cnt2;
            double coord_loss = 0.7 * (t8[6] / cnt_coord)
                              + 0.3 * (t8[7] / cnt_coord);
            double count_loss = t8[2] / (double)NB;
            double temp_reg   = fabs((double)__ldg(temp) - 1.0);
            double res_reg    = fabs((double)__ldg(resw) - 0.5);
            double total = coord_loss + 2.0 * edge_loss + 0.1 * count_loss
                         + 0.3 * sim_loss + 0.01 * (temp_reg + res_reg) + t8[3];
            out[0] = (float)total;
        }
    }
    __syncthreads();

    // ---- reset scratch for the next graph replay ----
    for (int k = tid; k < NB * 8; k += 256)
        ((double*)g_pair)[k] = 0.0;
    if (tid < NGRP) g_done1[tid] = 0;
    if (tid == 0) g_done2 = 0;
}

// ---------------------------------------------------------------------------
extern "C" void kernel_launch(void* const* d_in, const int* in_sizes, int n_in,
                              void* d_out, int out_size) {
    const float* pc      = (const float*)d_in[0];
    const float* adjm    = (const float*)d_in[1];
    const float* ncounts = (const float*)d_in[2];
    const float* rsim    = (const float*)d_in[3];
    const float* temp    = (const float*)d_in[4];
    const float* resw    = (const float*)d_in[5];
    const float* pts     = (const float*)d_in[6];
    const float* adj     = (const float*)d_in[7];
    const void*  mask    = d_in[8];

    fused_kernel<<<GRID, 256>>>(pc, adjm, ncounts, rsim, temp, resw,
                                pts, adj, mask, (float*)d_out);
    (void)in_sizes; (void)n_in; (void)out_size;
}

// round 15
// speedup vs baseline: 1.0767x; 1.0767x over previous
#include <cuda_runtime.h>
#include <cuda_bf16.h>
#include <math.h>

#define NB 64
#define NN 512
#define GRID 296
#define NWARP (GRID * 8)            // 2368
#define NGRP 37                     // 296 / 8
#define LN2 0.6931471805599453

// Scratch (__device__ globals; zeroed at load; re-zeroed by the last block)
__device__ double g_pair[NB][8];    // [2]=dot [3]=na2 [4]=aSum [5]=ent(log2) [6]=con
__device__ double g_part[GRID][4];  // per-block partials: edge, sim, mse, smooth
__device__ int    g_done1[NGRP];
__device__ int    g_done2;

// ---------------------------------------------------------------------------
// masked element op (last strip only): identity when !vb
__device__ __forceinline__ void lean_m(float p, float a, float s, bool vb,
                                       float& Px, float& Py, float& sim) {
    float w  = fmaf(-2.0f, p, 1.0f);
    float x0 = fmaf(a, w, p);
    float x  = vb ? x0 : 1.0f;
    float y  = vb ? 1.0f - x0 : 1.0f;
    float d  = vb ? s - a : 0.0f;
    Px *= x;
    Py *= y;
    sim = fmaf(d, d, sim);
}
// unmasked element op (strips known fully valid)
__device__ __forceinline__ void lean_u(float p, float a, float s,
                                       float& Px, float& Py, float& sim) {
    float x = fmaf(a, fmaf(-2.0f, p, 1.0f), p);
    Px *= x;
    Py *= 1.0f - x;
    float d = s - a;
    sim = fmaf(d, d, sim);
}

// ---------------------------------------------------------------------------
// One lean row with NS strips (NS = ceil(cnt4/32), 1..4).
template<int NS>
__device__ __forceinline__ void lean_row(
        const float4* __restrict__ pr, const float4* __restrict__ ar,
        const float4* __restrict__ sr, int lane, int cnt, int cnt4,
        double& accE, double& accS) {
    float Px = 1.f, Py = 1.f, sim = 0.f;
    const int cl = lane + 32 * (NS - 1);
    const int kl = min(cl, cnt4 - 1);
    float4 P[NS], A[NS], S[NS];
    #pragma unroll
    for (int k = 0; k < NS - 1; ++k) P[k] = __ldg(pr + lane + 32 * k);
    P[NS - 1] = __ldg(pr + kl);
    #pragma unroll
    for (int k = 0; k < NS - 1; ++k) A[k] = __ldg(ar + lane + 32 * k);
    A[NS - 1] = __ldg(ar + kl);
    #pragma unroll
    for (int k = 0; k < NS - 1; ++k) S[k] = __ldg(sr + lane + 32 * k);
    S[NS - 1] = __ldg(sr + kl);
    #pragma unroll
    for (int k = 0; k < NS - 1; ++k) {
        lean_u(P[k].x, A[k].x, S[k].x, Px, Py, sim);
        lean_u(P[k].y, A[k].y, S[k].y, Px, Py, sim);
        lean_u(P[k].z, A[k].z, S[k].z, Px, Py, sim);
        lean_u(P[k].w, A[k].w, S[k].w, Px, Py, sim);
    }
    lean_m(P[NS-1].x, A[NS-1].x, S[NS-1].x, 4 * cl + 0 < cnt, Px, Py, sim);
    lean_m(P[NS-1].y, A[NS-1].y, S[NS-1].y, 4 * cl + 1 < cnt, Px, Py, sim);
    lean_m(P[NS-1].z, A[NS-1].z, S[NS-1].z, 4 * cl + 2 < cnt, Px, Py, sim);
    lean_m(P[NS-1].w, A[NS-1].w, S[NS-1].w, 4 * cl + 3 < cnt, Px, Py, sim);
    accE += (double)fmaf(0.05f, __log2f(Px), 0.95f * __log2f(Py));
    accS += (double)sim;
}

// ---------------------------------------------------------------------------
__global__ __launch_bounds__(256, 2) void fused_kernel(
        const float* __restrict__ pc,      const float* __restrict__ adjm,
        const float* __restrict__ ncounts, const float* __restrict__ rsim,
        const float* __restrict__ temp,    const float* __restrict__ resw,
        const float* __restrict__ pts,     const float* __restrict__ adj,
        const void*  mask_raw,             float* __restrict__ out) {
    const int tid  = threadIdx.x;
    const int lane = tid & 31;
    const int w    = tid >> 5;
    const unsigned full = 0xffffffffu;

    __shared__ int s_cnt[NB];
    __shared__ int s_pref[NB + 1];

    // ---- all 64 mask counts (warp w: batches 8w..8w+7), 2 ballot rounds ----
    // (R13 path verbatim: reads only ~512B per batch, both rounds same lines)
    {
        const unsigned char* mb = (const unsigned char*)mask_raw;
        unsigned char c0 = mb[0], c1 = mb[1];   // elem (0,0) is always true
        int mode = (c1 != 0) ? 0 : ((c0 != 0) ? 1 : 2);
        auto rd = [&](int idx) -> bool {
            if (mode == 0)      return mb[idx] != 0;
            else if (mode == 1) return ((const int*)mask_raw)[idx] != 0;
            else                return ((const float*)mask_raw)[idx] != 0.0f;
        };
        bool on1[8];
        #pragma unroll
        for (int q = 0; q < 8; ++q)
            on1[q] = rd((w * 8 + q) * NN + lane * 16 + 15);
        int kk[8];
        #pragma unroll
        for (int q = 0; q < 8; ++q)
            kk[q] = __popc(__ballot_sync(full, on1[q]));
        bool on2[8];
        #pragma unroll
        for (int q = 0; q < 8; ++q)
            on2[q] = (kk[q] < 32 && lane < 16)
                   ? rd((w * 8 + q) * NN + 16 * kk[q] + lane) : false;
        #pragma unroll
        for (int q = 0; q < 8; ++q) {
            unsigned bal = __ballot_sync(full, on2[q]);
            int c = (kk[q] == 32) ? NN : 16 * kk[q] + __popc(bal & 0xFFFFu);
            if (lane == 0) s_cnt[w * 8 + q] = c;
        }
    }
    __syncthreads();

    // ---- prefix sum over the 64 counts (warp 0) ----
    if (w == 0) {
        int v0 = s_cnt[lane], v1 = s_cnt[lane + 32];
        int a0 = v0;
        #pragma unroll
        for (int o = 1; o < 32; o <<= 1) {
            int t = __shfl_up_sync(full, a0, o);
            if (lane >= o) a0 += t;
        }
        int tot0 = __shfl_sync(full, a0, 31);
        int a1 = v1;
        #pragma unroll
        for (int o = 1; o < 32; o <<= 1) {
            int t = __shfl_up_sync(full, a1, o);
            if (lane >= o) a1 += t;
        }
        a1 += tot0;
        s_pref[lane + 1]  = a0;
        s_pref[lane + 33] = a1;
        if (lane == 0) s_pref[0] = 0;
    }
    __syncthreads();
    const int R = s_pref[NB];

    double accE = 0.0, accS = 0.0, accM = 0.0, accSm = 0.0;
    const int gw = blockIdx.x * 8 + w;

    for (int u = gw; u < R + NB; u += NWARP) {
        if (u < R) {
            int lo = 0, hi = NB;
            #pragma unroll
            for (int it = 0; it < 6; ++it) {
                int mid = (lo + hi) >> 1;
                if (s_pref[mid] <= u) lo = mid; else hi = mid;
            }
            const int b   = lo;
            const int i   = u - s_pref[lo];
            const int cnt = s_cnt[b];
            const size_t rb = ((size_t)b * NN + i) * NN;

            if (cnt > 50) {
                const float4* pr = (const float4*)(adjm + rb);
                const float4* ar = (const float4*)(adj  + rb);
                const float4* sr = (const float4*)(rsim + rb);
                const int cnt4 = (cnt + 3) >> 2;
                const int ns = (cnt4 + 31) >> 5;
                switch (ns) {
                    case 1: lean_row<1>(pr, ar, sr, lane, cnt, cnt4, accE, accS); break;
                    case 2: lean_row<2>(pr, ar, sr, lane, cnt, cnt4, accE, accS); break;
                    case 3: lean_row<3>(pr, ar, sr, lane, cnt, cnt4, accE, accS); break;
                    default: lean_row<4>(pr, ar, sr, lane, cnt, cnt4, accE, accS); break;
                }
            } else {
                const int j0 = lane, j1 = lane + 32;
                const int mm = cnt - 1;
                const int k0 = min(j0, mm), k1 = min(j1, mm);
                float p0 = __ldg(adjm + rb + k0);
                float p1 = __ldg(adjm + rb + k1);
                float a0 = __ldg(adj  + rb + k0);
                float a1 = __ldg(adj  + rb + k1);
                float s0 = __ldg(rsim + rb + k0);
                float s1 = __ldg(rsim + rb + k1);
                const bool i0 = j0 >= cnt, i1 = j1 >= cnt;
                p0 = i0 ? 0.5f : p0;  a0 = i0 ? 0.f : a0;  s0 = i0 ? 0.f : s0;
                p1 = i1 ? 0.5f : p1;  a1 = i1 ? 0.f : a1;  s1 = i1 ? 0.f : s1;
                float sL=0,sM=0,sAt=0,sSim=0,sDot=0,sP2=0,sA=0,sPt=0,sCon=0;
                #pragma unroll
                for (int e = 0; e < 2; ++e) {
                    float p = e ? p1 : p0, a = e ? a1 : a0, s = e ? s1 : s0;
                    float L = __log2f(p), M = __log2f(1.0f - p);
                    float t = L - M;
                    sL += L; sM += M;
                    sAt = fmaf(a, t, sAt);
                    float ds = s - a;
                    sSim = fmaf(ds, ds, sSim);
                    sDot = fmaf(p, a, sDot);
                    sP2  = fmaf(p, p, sP2);
                    sA  += a;
                    sPt  = fmaf(p, t, sPt);
                    sCon += fabsf(p - 0.5f);
                }
                float inv = (i0 ? 1.f : 0.f) + (i1 ? 1.f : 0.f);
                sL += inv; sM += inv; sP2 -= 0.25f * inv;
                accE += (double)fmaf(0.05f, sL, fmaf(0.95f, sM, 0.9f * sAt));
                accS += (double)sSim;
                float v5[5] = {sDot, sP2, sA, sM + sPt, sCon};
                #pragma unroll
                for (int k = 0; k < 5; ++k)
                    #pragma unroll
                    for (int o = 16; o; o >>= 1)
                        v5[k] += __shfl_down_sync(full, v5[k], o);
                if (lane == 0) {
                    atomicAdd(&g_pair[b][2], (double)v5[0]);
                    atomicAdd(&g_pair[b][3], (double)v5[1]);
                    atomicAdd(&g_pair[b][4], (double)v5[2]);
                    atomicAdd(&g_pair[b][5], (double)v5[3]);
                    atomicAdd(&g_pair[b][6], (double)v5[4]);
                }
            }
        } else {
            const int b   = u - R;
            const int cnt = s_cnt[b];
            const float2* pc2  = (const float2*)pc + (size_t)b * NN;
            const float2* pts2 = (const float2*)pts + (size_t)b * NN;
            const int mm = cnt - 1;
            float mse = 0.f, smo = 0.f;
            for (int n0 = lane; n0 < cnt; n0 += 128) {
                const int n1 = n0 + 32, n2 = n0 + 64, n3 = n0 + 96;
                const int q1 = min(n1, mm);
                const int q2 = min(n2, mm), q3 = min(n3, mm);
                float2 u0 = __ldg(pc2 + n0);
                float2 u1 = __ldg(pc2 + q1);
                float2 u2 = __ldg(pc2 + q2);
                float2 u3 = __ldg(pc2 + q3);
                float2 v0 = __ldg(pts2 + n0);
                float2 v1 = __ldg(pts2 + q1);
                float2 v2 = __ldg(pts2 + q2);
                float2 v3 = __ldg(pts2 + q3);
                #define COORD1(UU,VV,NI) do {                                 \
                    bool vz = (NI) < cnt;                                     \
                    float dx = vz ? (UU.x - VV.x) : 0.f;                      \
                    float dy = vz ? (UU.y - VV.y) : 0.f;                      \
                    mse += dx * dx + dy * dy;                                 \
                    float ax = fabsf(dx), ay = fabsf(dy);                     \
                    smo += (ax < 1.0f ? 0.5f * dx * dx : ax - 0.5f)           \
                         + (ay < 1.0f ? 0.5f * dy * dy : ay - 0.5f); } while(0)
                COORD1(u0, v0, n0);
                COORD1(u1, v1, n1);
                COORD1(u2, v2, n2);
                COORD1(u3, v3, n3);
                #undef COORD1
            }
            accM  += (double)mse;
            accSm += (double)smo;
        }
    }

    // ---- block-reduce of the 4 accumulators -> contention-free STG ----
    {
        __shared__ double sh[8][4];
        double v[4] = {accE, accS, accM, accSm};
        #pragma unroll
        for (int k = 0; k < 4; ++k) {
            #pragma unroll
            for (int o = 16; o; o >>= 1) v[k] += __shfl_down_sync(full, v[k], o);
            if (lane == 0) sh[w][k] = v[k];
        }
        __syncthreads();
        if (w == 0 && lane < 4) {
            double xx = 0.0;
            #pragma unroll
            for (int ww = 0; ww < 8; ++ww) xx += sh[ww][lane];
            g_part[blockIdx.x][lane] = xx;        // plain STG, no contention
        }
    }

    // ---- hierarchical completion counter: 8-deep + 37-deep chains ----
    __shared__ int s_last;
    __threadfence();              // order this block's STGs + atomics
    __syncthreads();
    if (tid == 0) {
        s_last = 0;
        const int g = blockIdx.x >> 3;            // 37 groups of 8
        int o1 = atomicAdd(&g_done1[g], 1);
        if (o1 == 7) {
            int o2 = atomicAdd(&g_done2, 1);
            if (o2 == NGRP - 1) s_last = 1;
        }
    }
    __syncthreads();
    if (!s_last) return;
    __threadfence();

    // ---- finalize (last block only) ----
    double pe = 0.0, ps = 0.0, pm = 0.0, psm = 0.0;
    for (int blk = tid; blk < GRID; blk += 256) {
        pe  += g_part[blk][0];
        ps  += g_part[blk][1];
        pm  += g_part[blk][2];
        psm += g_part[blk][3];
    }
    double c2 = 0.0, cntd = 0.0, cl = 0.0, ac = 0.0;
    if (tid < NB) {
        int ci = s_cnt[tid];
        cntd   = (double)ci;
        c2     = cntd * cntd;
        double dc  = (double)__ldg(ncounts + tid) - cntd;
        double adc = fabs(dc);
        cl = (adc <= 1.0) ? 0.5 * dc * dc : adc - 0.5;
        if (ci > 5 && ci <= 50) {
            double dot  = g_pair[tid][2];
            double na2  = g_pair[tid][3];
            double nt2  = g_pair[tid][4];
            double entn = g_pair[tid][5] * LN2;
            double con  = g_pair[tid][6];
            double na   = sqrt(na2), nt = sqrt(nt2);
            double cosv = dot / (fmax(na, 1e-8) * fmax(nt, 1e-8));
            double n2   = fmax(c2, 1.0);
            ac = (-cosv - 0.2 * (con / n2)) + 0.1 * (-entn / n2);
        }
    }
    {
        __shared__ double sh2[8][8];
        double v[8] = {c2, cntd, cl, ac, pe, ps, pm, psm};
        #pragma unroll
        for (int k = 0; k < 8; ++k) {
            #pragma unroll
            for (int o = 16; o; o >>= 1) v[k] += __shfl_down_sync(full, v[k], o);
            if (lane == 0) sh2[w][k] = v[k];
        }
        __syncthreads();
        if (tid == 0) {
            double t8[8];
            #pragma unroll
            for (int k = 0; k < 8; ++k) {
                double xx = 0.0;
                #pragma unroll
                for (int ww = 0; ww < 8; ++ww) xx += sh2[ww][k];
                t8[k] = xx;
            }
            double cnt2       = fmax(t8[0], 1.0);
            double cnt_coord  = fmax(t8[1] * 2.0, 1.0);
            double edge_loss  = -(t8[4] * LN2) / cnt2;
            double sim_loss   = t8[5] / cnt2;
            double coord_loss = 0.7 * (t8[6] / cnt_coord)
                              + 0.3 * (t8[7] / cnt_coord);
            double count_loss = t8[2] / (double)NB;
            double temp_reg   = fabs((double)__ldg(temp) - 1.0);
            double res_reg    = fabs((double)__ldg(resw) - 0.5);
            double total = coord_loss + 2.0 * edge_loss + 0.1 * count_loss
                         + 0.3 * sim_loss + 0.01 * (temp_reg + res_reg) + t8[3];
            out[0] = (float)total;
        }
    }
    __syncthreads();

    // ---- reset scratch for the next graph replay ----
    for (int k = tid; k < NB * 8; k += 256)
        ((double*)g_pair)[k] = 0.0;
    if (tid < NGRP) g_done1[tid] = 0;
    if (tid == 0) g_done2 = 0;
}

// ---------------------------------------------------------------------------
extern "C" void kernel_launch(void* const* d_in, const int* in_sizes, int n_in,
                              void* d_out, int out_size) {
    const float* pc      = (const float*)d_in[0];
    const float* adjm    = (const float*)d_in[1];
    const float* ncounts = (const float*)d_in[2];
    const float* rsim    = (const float*)d_in[3];
    const float* temp    = (const float*)d_in[4];
    const float* resw    = (const float*)d_in[5];
    const float* pts     = (const float*)d_in[6];
    const float* adj     = (const float*)d_in[7];
    const void*  mask    = d_in[8];

    fused_kernel<<<GRID, 256>>>(pc, adjm, ncounts, rsim, temp, resw,
                                pts, adj, mask, (float*)d_out);
    (void)in_sizes; (void)n_in; (void)out_size;
}

// round 16
// speedup vs baseline: 1.1829x; 1.0986x over previous
#include <cuda_runtime.h>
#include <cuda_bf16.h>
#include <math.h>

#define NB 64
#define NN 512
#define GRID 296
#define NWARP (GRID * 8)            // 2368
#define LN2 0.6931471805599453

// Scratch (__device__ globals; zeroed at load; re-zeroed by the last block)
__device__ double g_pair[NB][8];    // [2]=dot [3]=na2 [4]=aSum [5]=ent(log2) [6]=con
__device__ double g_tot[8];         // 0=edge(log2) 1=sim 2=mse 3=smooth
__device__ int    g_done;

// ---------------------------------------------------------------------------
// masked element op (last strip only): identity when !vb
__device__ __forceinline__ void lean_m(float p, float a, float s, bool vb,
                                       float& Px, float& Py, float& sim) {
    float w  = fmaf(-2.0f, p, 1.0f);
    float x0 = fmaf(a, w, p);
    float x  = vb ? x0 : 1.0f;
    float y  = vb ? 1.0f - x0 : 1.0f;
    float d  = vb ? s - a : 0.0f;
    Px *= x;
    Py *= y;
    sim = fmaf(d, d, sim);
}
// unmasked element op (strips known fully valid)
__device__ __forceinline__ void lean_u(float p, float a, float s,
                                       float& Px, float& Py, float& sim) {
    float x = fmaf(a, fmaf(-2.0f, p, 1.0f), p);
    Px *= x;
    Py *= 1.0f - x;
    float d = s - a;
    sim = fmaf(d, d, sim);
}

// ---------------------------------------------------------------------------
// One lean row with NS strips (NS = ceil(cnt4/32), 1..4).
template<int NS>
__device__ __forceinline__ void lean_row(
        const float4* __restrict__ pr, const float4* __restrict__ ar,
        const float4* __restrict__ sr, int lane, int cnt, int cnt4,
        double& accE, double& accS) {
    float Px = 1.f, Py = 1.f, sim = 0.f;
    const int cl = lane + 32 * (NS - 1);
    const int kl = min(cl, cnt4 - 1);
    float4 P[NS], A[NS], S[NS];
    #pragma unroll
    for (int k = 0; k < NS - 1; ++k) P[k] = __ldg(pr + lane + 32 * k);
    P[NS - 1] = __ldg(pr + kl);
    #pragma unroll
    for (int k = 0; k < NS - 1; ++k) A[k] = __ldg(ar + lane + 32 * k);
    A[NS - 1] = __ldg(ar + kl);
    #pragma unroll
    for (int k = 0; k < NS - 1; ++k) S[k] = __ldg(sr + lane + 32 * k);
    S[NS - 1] = __ldg(sr + kl);
    #pragma unroll
    for (int k = 0; k < NS - 1; ++k) {
        lean_u(P[k].x, A[k].x, S[k].x, Px, Py, sim);
        lean_u(P[k].y, A[k].y, S[k].y, Px, Py, sim);
        lean_u(P[k].z, A[k].z, S[k].z, Px, Py, sim);
        lean_u(P[k].w, A[k].w, S[k].w, Px, Py, sim);
    }
    lean_m(P[NS-1].x, A[NS-1].x, S[NS-1].x, 4 * cl + 0 < cnt, Px, Py, sim);
    lean_m(P[NS-1].y, A[NS-1].y, S[NS-1].y, 4 * cl + 1 < cnt, Px, Py, sim);
    lean_m(P[NS-1].z, A[NS-1].z, S[NS-1].z, 4 * cl + 2 < cnt, Px, Py, sim);
    lean_m(P[NS-1].w, A[NS-1].w, S[NS-1].w, 4 * cl + 3 < cnt, Px, Py, sim);
    accE += (double)fmaf(0.05f, __log2f(Px), 0.95f * __log2f(Py));
    accS += (double)sim;
}

// ---------------------------------------------------------------------------
__global__ __launch_bounds__(256, 2) void fused_kernel(
        const float* __restrict__ pc,      const float* __restrict__ adjm,
        const float* __restrict__ ncounts, const float* __restrict__ rsim,
        const float* __restrict__ temp,    const float* __restrict__ resw,
        const float* __restrict__ pts,     const float* __restrict__ adj,
        const void*  mask_raw,             float* __restrict__ out) {
    const int tid  = threadIdx.x;
    const int lane = tid & 31;
    const int w    = tid >> 5;
    const unsigned full = 0xffffffffu;

    __shared__ int s_cnt[NB];
    __shared__ int s_pref[NB + 1];

    // ---- all 64 mask counts (warp w: batches 8w..8w+7), 2 ballot rounds ----
    {
        const unsigned char* mb = (const unsigned char*)mask_raw;
        unsigned char c0 = mb[0], c1 = mb[1];   // elem (0,0) is always true
        int mode = (c1 != 0) ? 0 : ((c0 != 0) ? 1 : 2);
        auto rd = [&](int idx) -> bool {
            if (mode == 0)      return mb[idx] != 0;
            else if (mode == 1) return ((const int*)mask_raw)[idx] != 0;
            else                return ((const float*)mask_raw)[idx] != 0.0f;
        };
        bool on1[8];
        #pragma unroll
        for (int q = 0; q < 8; ++q)
            on1[q] = rd((w * 8 + q) * NN + lane * 16 + 15);
        int kk[8];
        #pragma unroll
        for (int q = 0; q < 8; ++q)
            kk[q] = __popc(__ballot_sync(full, on1[q]));
        bool on2[8];
        #pragma unroll
        for (int q = 0; q < 8; ++q)
            on2[q] = (kk[q] < 32 && lane < 16)
                   ? rd((w * 8 + q) * NN + 16 * kk[q] + lane) : false;
        #pragma unroll
        for (int q = 0; q < 8; ++q) {
            unsigned bal = __ballot_sync(full, on2[q]);
            int c = (kk[q] == 32) ? NN : 16 * kk[q] + __popc(bal & 0xFFFFu);
            if (lane == 0) s_cnt[w * 8 + q] = c;
        }
    }
    __syncthreads();

    // ---- prefix sum over the 64 counts (warp 0) ----
    if (w == 0) {
        int v0 = s_cnt[lane], v1 = s_cnt[lane + 32];
        int a0 = v0;
        #pragma unroll
        for (int o = 1; o < 32; o <<= 1) {
            int t = __shfl_up_sync(full, a0, o);
            if (lane >= o) a0 += t;
        }
        int tot0 = __shfl_sync(full, a0, 31);
        int a1 = v1;
        #pragma unroll
        for (int o = 1; o < 32; o <<= 1) {
            int t = __shfl_up_sync(full, a1, o);
            if (lane >= o) a1 += t;
        }
        a1 += tot0;
        s_pref[lane + 1]  = a0;
        s_pref[lane + 33] = a1;
        if (lane == 0) s_pref[0] = 0;
    }
    __syncthreads();
    const int R = s_pref[NB];

    double accE = 0.0, accS = 0.0, accM = 0.0, accSm = 0.0;
    const int gw = blockIdx.x * 8 + w;

    for (int u = gw; u < R + NB; u += NWARP) {
        if (u < R) {
            int lo = 0, hi = NB;
            #pragma unroll
            for (int it = 0; it < 6; ++it) {
                int mid = (lo + hi) >> 1;
                if (s_pref[mid] <= u) lo = mid; else hi = mid;
            }
            const int b   = lo;
            const int i   = u - s_pref[lo];
            const int cnt = s_cnt[b];
            const size_t rb = ((size_t)b * NN + i) * NN;

            if (cnt > 50) {
                const float4* pr = (const float4*)(adjm + rb);
                const float4* ar = (const float4*)(adj  + rb);
                const float4* sr = (const float4*)(rsim + rb);
                const int cnt4 = (cnt + 3) >> 2;
                const int ns = (cnt4 + 31) >> 5;
                switch (ns) {
                    case 1: lean_row<1>(pr, ar, sr, lane, cnt, cnt4, accE, accS); break;
                    case 2: lean_row<2>(pr, ar, sr, lane, cnt, cnt4, accE, accS); break;
                    case 3: lean_row<3>(pr, ar, sr, lane, cnt, cnt4, accE, accS); break;
                    default: lean_row<4>(pr, ar, sr, lane, cnt, cnt4, accE, accS); break;
                }
            } else {
                const int j0 = lane, j1 = lane + 32;
                const int mm = cnt - 1;
                const int k0 = min(j0, mm), k1 = min(j1, mm);
                float p0 = __ldg(adjm + rb + k0);
                float p1 = __ldg(adjm + rb + k1);
                float a0 = __ldg(adj  + rb + k0);
                float a1 = __ldg(adj  + rb + k1);
                float s0 = __ldg(rsim + rb + k0);
                float s1 = __ldg(rsim + rb + k1);
                const bool i0 = j0 >= cnt, i1 = j1 >= cnt;
                p0 = i0 ? 0.5f : p0;  a0 = i0 ? 0.f : a0;  s0 = i0 ? 0.f : s0;
                p1 = i1 ? 0.5f : p1;  a1 = i1 ? 0.f : a1;  s1 = i1 ? 0.f : s1;
                float sL=0,sM=0,sAt=0,sSim=0,sDot=0,sP2=0,sA=0,sPt=0,sCon=0;
                #pragma unroll
                for (int e = 0; e < 2; ++e) {
                    float p = e ? p1 : p0, a = e ? a1 : a0, s = e ? s1 : s0;
                    float L = __log2f(p), M = __log2f(1.0f - p);
                    float t = L - M;
                    sL += L; sM += M;
                    sAt = fmaf(a, t, sAt);
                    float ds = s - a;
                    sSim = fmaf(ds, ds, sSim);
                    sDot = fmaf(p, a, sDot);
                    sP2  = fmaf(p, p, sP2);
                    sA  += a;
                    sPt  = fmaf(p, t, sPt);
                    sCon += fabsf(p - 0.5f);
                }
                float inv = (i0 ? 1.f : 0.f) + (i1 ? 1.f : 0.f);
                sL += inv; sM += inv; sP2 -= 0.25f * inv;
                accE += (double)fmaf(0.05f, sL, fmaf(0.95f, sM, 0.9f * sAt));
                accS += (double)sSim;
                float v5[5] = {sDot, sP2, sA, sM + sPt, sCon};
                #pragma unroll
                for (int k = 0; k < 5; ++k)
                    #pragma unroll
                    for (int o = 16; o; o >>= 1)
                        v5[k] += __shfl_down_sync(full, v5[k], o);
                if (lane == 0) {
                    atomicAdd(&g_pair[b][2], (double)v5[0]);
                    atomicAdd(&g_pair[b][3], (double)v5[1]);
                    atomicAdd(&g_pair[b][4], (double)v5[2]);
                    atomicAdd(&g_pair[b][5], (double)v5[3]);
                    atomicAdd(&g_pair[b][6], (double)v5[4]);
                }
            }
        } else {
            const int b   = u - R;
            const int cnt = s_cnt[b];
            const float2* pc2  = (const float2*)pc + (size_t)b * NN;
            const float2* pts2 = (const float2*)pts + (size_t)b * NN;
            const int mm = cnt - 1;
            float mse = 0.f, smo = 0.f;
            for (int n0 = lane; n0 < cnt; n0 += 128) {
                const int n1 = n0 + 32, n2 = n0 + 64, n3 = n0 + 96;
                const int q1 = min(n1, mm);
                const int q2 = min(n2, mm), q3 = min(n3, mm);
                float2 u0 = __ldg(pc2 + n0);
                float2 u1 = __ldg(pc2 + q1);
                float2 u2 = __ldg(pc2 + q2);
                float2 u3 = __ldg(pc2 + q3);
                float2 v0 = __ldg(pts2 + n0);
                float2 v1 = __ldg(pts2 + q1);
                float2 v2 = __ldg(pts2 + q2);
                float2 v3 = __ldg(pts2 + q3);
                #define COORD1(UU,VV,NI) do {                                 \
                    bool vz = (NI) < cnt;                                     \
                    float dx = vz ? (UU.x - VV.x) : 0.f;                      \
                    float dy = vz ? (UU.y - VV.y) : 0.f;                      \
                    mse += dx * dx + dy * dy;                                 \
                    float ax = fabsf(dx), ay = fabsf(dy);                     \
                    smo += (ax < 1.0f ? 0.5f * dx * dx : ax - 0.5f)           \
                         + (ay < 1.0f ? 0.5f * dy * dy : ay - 0.5f); } while(0)
                COORD1(u0, v0, n0);
                COORD1(u1, v1, n1);
                COORD1(u2, v2, n2);
                COORD1(u3, v3, n3);
                #undef COORD1
            }
            accM  += (double)mse;
            accSm += (double)smo;
        }
    }

    // ---- single block-reduce of the 4 global accumulators ----
    {
        __shared__ double sh[8][4];
        double v[4] = {accE, accS, accM, accSm};
        #pragma unroll
        for (int k = 0; k < 4; ++k) {
            #pragma unroll
            for (int o = 16; o; o >>= 1) v[k] += __shfl_down_sync(full, v[k], o);
            if (lane == 0) sh[w][k] = v[k];
        }
        __syncthreads();
        if (w == 0 && lane < 4) {
            double xx = 0.0;
            #pragma unroll
            for (int ww = 0; ww < 8; ++ww) xx += sh[ww][lane];
            atomicAdd(&g_tot[lane], xx);
        }
    }

    // ---- completion counter: last block finalizes ----
    __shared__ int s_last;
    __threadfence();
    __syncthreads();
    if (tid == 0) {
        int done = atomicAdd(&g_done, 1);
        s_last = (done == GRID - 1) ? 1 : 0;
    }
    __syncthreads();
    if (!s_last) return;
    __threadfence();

    // ---- finalize (thread t<NB handles batch t) ----
    double c2 = 0.0, cntd = 0.0, cl = 0.0, ac = 0.0;
    if (tid < NB) {
        int ci = s_cnt[tid];
        cntd   = (double)ci;
        c2     = cntd * cntd;
        double dc  = (double)__ldg(ncounts + tid) - cntd;
        double adc = fabs(dc);
        cl = (adc <= 1.0) ? 0.5 * dc * dc : adc - 0.5;
        if (ci > 5 && ci <= 50) {
            double dot  = g_pair[tid][2];
            double na2  = g_pair[tid][3];
            double nt2  = g_pair[tid][4];
            double entn = g_pair[tid][5] * LN2;
            double con  = g_pair[tid][6];
            double na   = sqrt(na2), nt = sqrt(nt2);
            double cosv = dot / (fmax(na, 1e-8) * fmax(nt, 1e-8));
            double n2   = fmax(c2, 1.0);
            ac = (-cosv - 0.2 * (con / n2)) + 0.1 * (-entn / n2);
        }
    }
    {
        __shared__ double sh2[8][4];
        double v[4] = {c2, cntd, cl, ac};
        #pragma unroll
        for (int k = 0; k < 4; ++k) {
            #pragma unroll
            for (int o = 16; o; o >>= 1) v[k] += __shfl_down_sync(full, v[k], o);
            if (lane == 0) sh2[w][k] = v[k];
        }
        __syncthreads();
        if (tid == 0) {
            double t4[4];
            #pragma unroll
            for (int k = 0; k < 4; ++k) {
                double xx = 0.0;
                #pragma unroll
                for (int ww = 0; ww < 8; ++ww) xx += sh2[ww][k];
                t4[k] = xx;
            }
            double cnt2       = fmax(t4[0], 1.0);
            double cnt_coord  = fmax(t4[1] * 2.0, 1.0);
            double edge_loss  = -(g_tot[0] * LN2) / cnt2;
            double sim_loss   = g_tot[1] / cnt2;
            double coord_loss = 0.7 * (g_tot[2] / cnt_coord)
                              + 0.3 * (g_tot[3] / cnt_coord);
            double count_loss = t4[2] / (double)NB;
            double temp_reg   = fabs((double)__ldg(temp) - 1.0);
            double res_reg    = fabs((double)__ldg(resw) - 0.5);
            double total = coord_loss + 2.0 * edge_loss + 0.1 * count_loss
                         + 0.3 * sim_loss + 0.01 * (temp_reg + res_reg) + t4[3];
            out[0] = (float)total;
        }
    }
    __syncthreads();

    // ---- reset scratch for the next graph replay ----
    for (int k = tid; k < NB * 8; k += 256)
        ((double*)g_pair)[k] = 0.0;
    if (tid < 8) g_tot[tid] = 0.0;
    if (tid == 0) g_done = 0;
}

// ---------------------------------------------------------------------------
extern "C" void kernel_launch(void* const* d_in, const int* in_sizes, int n_in,
                              void* d_out, int out_size) {
    const float* pc      = (const float*)d_in[0];
    const float* adjm    = (const float*)d_in[1];
    const float* ncounts = (const float*)d_in[2];
    const float* rsim    = (const float*)d_in[3];
    const float* temp    = (const float*)d_in[4];
    const float* resw    = (const float*)d_in[5];
    const float* pts     = (const float*)d_in[6];
    const float* adj     = (const float*)d_in[7];
    const void*  mask    = d_in[8];

    fused_kernel<<<GRID, 256>>>(pc, adjm, ncounts, rsim, temp, resw,
                                pts, adj, mask, (float*)d_out);
    (void)in_sizes; (void)n_in; (void)out_size;
}